// round 15
// baseline (speedup 1.0000x reference)
#include <cuda_runtime.h>
#include <cuda_bf16.h>
#include <math.h>
#include <stdint.h>

#define BB 4
#define LL 2048
#define DD 1024
#define HH 16
#define DHH 64

typedef __nv_bfloat16 bf16;

// ---------------- scratch (allocation-free device globals) ----------------
__device__ bf16 g_xh[(size_t)8192 * 1024], g_xl[(size_t)8192 * 1024];
__device__ bf16 g_wqh[(size_t)3072 * 1024], g_wql[(size_t)3072 * 1024];
__device__ bf16 g_wph[(size_t)1024 * 1024], g_wpl[(size_t)1024 * 1024];
__device__ bf16 g_qh[(size_t)64 * 2048 * 64], g_ql[(size_t)64 * 2048 * 64];
__device__ bf16 g_kh[(size_t)64 * 2048 * 64], g_kl[(size_t)64 * 2048 * 64];
__device__ bf16 g_vh[(size_t)64 * 2048 * 64], g_vl[(size_t)64 * 2048 * 64];
__device__ bf16 g_ctxh[(size_t)8192 * 1024], g_ctxl[(size_t)8192 * 1024];

// ---------------- PTX helpers ----------------
__device__ __forceinline__ uint32_t smem_u32(const void* p) {
    uint32_t a;
    asm("{ .reg .u64 t; cvta.to.shared.u64 t, %1; cvt.u32.u64 %0, t; }"
        : "=r"(a) : "l"(p));
    return a;
}
__device__ __forceinline__ void ldsm_x4(uint32_t* r, uint32_t addr) {
    asm volatile("ldmatrix.sync.aligned.m8n8.x4.shared.b16 {%0,%1,%2,%3}, [%4];"
                 : "=r"(r[0]), "=r"(r[1]), "=r"(r[2]), "=r"(r[3]) : "r"(addr));
}
__device__ __forceinline__ void ldsm_x4_t(uint32_t* r, uint32_t addr) {
    asm volatile("ldmatrix.sync.aligned.m8n8.x4.trans.shared.b16 {%0,%1,%2,%3}, [%4];"
                 : "=r"(r[0]), "=r"(r[1]), "=r"(r[2]), "=r"(r[3]) : "r"(addr));
}
__device__ __forceinline__ void mma_bf16(float* d, const uint32_t* a,
                                         const uint32_t* b) {
    asm volatile(
        "mma.sync.aligned.m16n8k16.row.col.f32.bf16.bf16.f32 "
        "{%0,%1,%2,%3}, {%4,%5,%6,%7}, {%8,%9}, {%0,%1,%2,%3};"
        : "+f"(d[0]), "+f"(d[1]), "+f"(d[2]), "+f"(d[3])
        : "r"(a[0]), "r"(a[1]), "r"(a[2]), "r"(a[3]), "r"(b[0]), "r"(b[1]));
}
#define CP_ASYNC16(dst, src) \
    asm volatile("cp.async.cg.shared.global [%0], [%1], 16;" \
                 :: "r"(dst), "l"(src) : "memory")
#define CP_COMMIT() asm volatile("cp.async.commit_group;" ::: "memory")
#define CP_WAIT0()  asm volatile("cp.async.wait_group 0;" ::: "memory")

__device__ __forceinline__ uint32_t pack_bf16x2(float a, float b) {
    __nv_bfloat162 t = __floats2bfloat162_rn(a, b);
    return *(uint32_t*)&t;
}
__device__ __forceinline__ void split_bf16(float v, bf16& h, bf16& l) {
    h = __float2bfloat16(v);
    l = __float2bfloat16(v - __bfloat162float(h));
}

// ---------------------------------------------------------------------------
// conv_split: fp32 -> (hi, lo) bf16, elementwise
// ---------------------------------------------------------------------------
__global__ void conv_split(const float* __restrict__ src, bf16* __restrict__ h,
                           bf16* __restrict__ l, int n4)
{
    int i = blockIdx.x * blockDim.x + threadIdx.x;
    if (i >= n4) return;
    float4 v = ((const float4*)src)[i];
    bf16 h0, l0, h1, l1, h2, l2, h3, l3;
    split_bf16(v.x, h0, l0); split_bf16(v.y, h1, l1);
    split_bf16(v.z, h2, l2); split_bf16(v.w, h3, l3);
    ((__nv_bfloat162*)h)[2 * i]     = __nv_bfloat162(h0, h1);
    ((__nv_bfloat162*)h)[2 * i + 1] = __nv_bfloat162(h2, h3);
    ((__nv_bfloat162*)l)[2 * i]     = __nv_bfloat162(l0, l1);
    ((__nv_bfloat162*)l)[2 * i + 1] = __nv_bfloat162(l2, l3);
}

// ---------------------------------------------------------------------------
// HMMA GEMM, tile 128x128, K-CHUNK 64 => 192 MMAs/warp per barrier interval
// (flash-parity amortization). 2-stage cp.async, flash-style schedule:
// wait0 -> sync -> issue(ch+1) -> compute(ch). Pitch-72 rows (144 B,
// conflict-free ldmatrix). 8 warps (2x4), warp 64x32.
// mode 0: scatter bf16 hi/lo into g_q/g_k/g_v (q scaled). mode 1: fp32 -> Cp.
// ---------------------------------------------------------------------------
#define GW 72                        // smem pitch in bf16 elems (144 B)
#define GMAT (128 * GW * 2)          // 18432 B per matrix tile (128 x 64 bf16)
#define GSTAGE (4 * GMAT)            // 73728 B per stage
#define GEMM_SMEM (2 * GSTAGE)       // 147456 B

__global__ __launch_bounds__(256) void hmma_gemm(
    const bf16* __restrict__ Ah_g, const bf16* __restrict__ Al_g,
    const bf16* __restrict__ Bh_g, const bf16* __restrict__ Bl_g,
    float* __restrict__ Cp, int ldc, int mode)
{
    extern __shared__ char smem[];
    const uint32_t sb = smem_u32(smem);

    const int tid  = threadIdx.x;
    const int wid  = tid >> 5;
    const int lane = tid & 31;
    const int m0   = blockIdx.y * 128;
    const int n0   = blockIdx.x * 128;
    const int wm   = (wid >> 2) * 64;   // 2 warps in m
    const int wn   = (wid & 3) * 32;    // 4 warps in n

    const bf16* mats[4] = {Ah_g, Al_g, Bh_g, Bl_g};

    // cp.async mapping: 4 mats x 128 rows x 8 parts(16B) = 4096 segs,
    // 16 per thread. i = it*256+tid: mat=i>>10, r=(i>>3)&127, part=i&7.
    auto issue_chunk = [&](int ch, int stage) {
        const int k0 = ch * 64;
        const uint32_t stg = sb + stage * GSTAGE;
        #pragma unroll
        for (int it = 0; it < 16; it++) {
            int i = it * 256 + tid;
            int mat = i >> 10, r = (i >> 3) & 127, part = i & 7;
            int grow = (mat < 2) ? (m0 + r) : (n0 + r);
            const bf16* src = mats[mat] + (size_t)grow * 1024 + k0 + part * 8;
            uint32_t dst = stg + mat * GMAT + r * (GW * 2) + part * 16;
            CP_ASYNC16(dst, src);
        }
        CP_COMMIT();
    };

    float c[4][4][4] = {};   // [mt][nt][4]

    issue_chunk(0, 0);

    for (int ch = 0; ch < 16; ch++) {
        CP_WAIT0();
        __syncthreads();

        if (ch + 1 < 16) issue_chunk(ch + 1, (ch + 1) & 1);

        const uint32_t stg = sb + (ch & 1) * GSTAGE;
        const uint32_t sAh = stg, sAl = stg + GMAT;
        const uint32_t sBh = stg + 2 * GMAT, sBl = stg + 3 * GMAT;

        #pragma unroll
        for (int ks = 0; ks < 4; ks++) {
            const uint32_t kc = (uint32_t)(ks * 32 + (lane >> 4) * 16);

            // B fragments: loaded once per ks, reused by all 4 mt
            uint32_t bh[4][2], bl[4][2];
            #pragma unroll
            for (int half = 0; half < 2; half++) {
                uint32_t r4h[4], r4l[4];
                uint32_t off = (uint32_t)(wn + half * 16 + (lane & 15)) * (GW * 2) + kc;
                ldsm_x4(r4h, sBh + off);
                ldsm_x4(r4l, sBl + off);
                bh[half * 2 + 0][0] = r4h[0]; bh[half * 2 + 0][1] = r4h[2];
                bh[half * 2 + 1][0] = r4h[1]; bh[half * 2 + 1][1] = r4h[3];
                bl[half * 2 + 0][0] = r4l[0]; bl[half * 2 + 0][1] = r4l[2];
                bl[half * 2 + 1][0] = r4l[1]; bl[half * 2 + 1][1] = r4l[3];
            }

            #pragma unroll
            for (int mt = 0; mt < 4; mt++) {
                uint32_t ah[4], al[4];
                uint32_t off = (uint32_t)(wm + mt * 16 + (lane & 15)) * (GW * 2) + kc;
                ldsm_x4(ah, sAh + off);
                ldsm_x4(al, sAl + off);
                #pragma unroll
                for (int nt = 0; nt < 4; nt++) {
                    mma_bf16(c[mt][nt], ah, bh[nt]);
                    mma_bf16(c[mt][nt], ah, bl[nt]);
                    mma_bf16(c[mt][nt], al, bh[nt]);
                }
            }
        }
    }

    const int erow = lane >> 2;
    const int ecol = (lane & 3) * 2;

    if (mode == 1) {
        #pragma unroll
        for (int mt = 0; mt < 4; mt++)
            #pragma unroll
            for (int nt = 0; nt < 4; nt++) {
                int row = m0 + wm + mt * 16 + erow;
                int col = n0 + wn + nt * 8 + ecol;
                *(float2*)&Cp[(size_t)row * ldc + col] =
                    make_float2(c[mt][nt][0], c[mt][nt][1]);
                *(float2*)&Cp[(size_t)(row + 8) * ldc + col] =
                    make_float2(c[mt][nt][2], c[mt][nt][3]);
            }
    } else {
        const int which = n0 >> 10;
        bf16* dsth = (which == 0) ? g_qh : (which == 1) ? g_kh : g_vh;
        bf16* dstl = (which == 0) ? g_ql : (which == 1) ? g_kl : g_vl;
        const float sc = (which == 0) ? 0.125f : 1.0f;
        #pragma unroll
        for (int mt = 0; mt < 4; mt++)
            #pragma unroll
            for (int nt = 0; nt < 4; nt++) {
                int col = (n0 & 1023) + wn + nt * 8 + ecol;
                int h = col >> 6, dh = col & 63;
                #pragma unroll
                for (int rr = 0; rr < 2; rr++) {
                    int row = m0 + wm + mt * 16 + erow + rr * 8;
                    int b = row >> 11, l = row & 2047;
                    size_t base = ((size_t)((b << 4) + h) * 2048 + l) * 64 + dh;
                    float v0 = c[mt][nt][rr * 2 + 0] * sc;
                    float v1 = c[mt][nt][rr * 2 + 1] * sc;
                    bf16 h0, l0, h1, l1;
                    split_bf16(v0, h0, l0);
                    split_bf16(v1, h1, l1);
                    *(__nv_bfloat162*)(dsth + base) = __nv_bfloat162(h0, h1);
                    *(__nv_bfloat162*)(dstl + base) = __nv_bfloat162(l0, l1);
                }
            }
    }
}

// ---------------------------------------------------------------------------
// Flash attention, HMMA (unchanged).
// ---------------------------------------------------------------------------
#define FP 72
#define FQ (128 * FP * 2)
#define FMAT (64 * FP * 2)
#define FSTAGE (4 * FMAT)
#define FLASH_SMEM (2 * FQ + 2 * FSTAGE)

__global__ __launch_bounds__(256) void flash_hmma()
{
    extern __shared__ char smem[];
    const uint32_t sb = smem_u32(smem);
    const uint32_t sQh = sb, sQl = sb + FQ;
    const uint32_t sKV = sb + 2 * FQ;

    const int tid  = threadIdx.x;
    const int wid  = tid >> 5;
    const int lane = tid & 31;
    const int bh   = blockIdx.y;
    const int q0   = blockIdx.x * 128;
    const int b    = bh >> 4;
    const int h    = bh & 15;

    const bf16* kvg[4] = {g_kh + (size_t)bh * 2048 * 64, g_kl + (size_t)bh * 2048 * 64,
                          g_vh + (size_t)bh * 2048 * 64, g_vl + (size_t)bh * 2048 * 64};

    {
        const bf16* qh_g = g_qh + (size_t)bh * 2048 * 64;
        const bf16* ql_g = g_ql + (size_t)bh * 2048 * 64;
        #pragma unroll
        for (int it = 0; it < 4; it++) {
            int i = tid + it * 256;
            int r = i >> 3, part = i & 7;
            uint4 v = *(const uint4*)(qh_g + (size_t)(q0 + r) * 64 + part * 8);
            *(uint4*)(smem + r * (FP * 2) + part * 16) = v;
            uint4 w = *(const uint4*)(ql_g + (size_t)(q0 + r) * 64 + part * 8);
            *(uint4*)(smem + FQ + r * (FP * 2) + part * 16) = w;
        }
    }

    #pragma unroll
    for (int it = 0; it < 8; it++) {
        int i = tid + it * 256;
        int mat = i >> 9, r = (i >> 3) & 63, part = i & 7;
        const bf16* src = kvg[mat] + (size_t)r * 64 + part * 8;
        uint32_t dst = sKV + mat * FMAT + r * (FP * 2) + part * 16;
        CP_ASYNC16(dst, src);
    }
    CP_COMMIT();
    __syncthreads();

    uint32_t qh[4][4], ql[4][4];
    #pragma unroll
    for (int ks = 0; ks < 4; ks++) {
        uint32_t off = (uint32_t)(wid * 16 + (lane & 15)) * (FP * 2)
                     + ks * 32 + (lane >> 4) * 16;
        ldsm_x4(qh[ks], sQh + off);
        ldsm_x4(ql[ks], sQl + off);
    }

    float o[8][4] = {};
    float mrow[2] = {-1e30f, -1e30f};
    float lrow[2] = {0.f, 0.f};

    for (int kb = 0; kb < 32; kb++) {
        CP_WAIT0();
        __syncthreads();

        if (kb + 1 < 32) {
            const uint32_t stg = sKV + ((kb + 1) & 1) * FSTAGE;
            const int krow0 = (kb + 1) * 64;
            #pragma unroll
            for (int it = 0; it < 8; it++) {
                int i = tid + it * 256;
                int mat = i >> 9, r = (i >> 3) & 63, part = i & 7;
                const bf16* src = kvg[mat] + (size_t)(krow0 + r) * 64 + part * 8;
                uint32_t dst = stg + mat * FMAT + r * (FP * 2) + part * 16;
                CP_ASYNC16(dst, src);
            }
            CP_COMMIT();
        }

        const uint32_t stg = sKV + (kb & 1) * FSTAGE;
        const uint32_t sKh = stg, sKl = stg + FMAT;
        const uint32_t sVh = stg + 2 * FMAT, sVl = stg + 3 * FMAT;

        float s[8][4] = {};
        #pragma unroll
        for (int ks = 0; ks < 4; ks++) {
            const uint32_t kc = (uint32_t)(ks * 32 + (lane >> 4) * 16);
            #pragma unroll
            for (int p = 0; p < 4; p++) {
                uint32_t kh4[4], kl4[4];
                uint32_t off = (uint32_t)(p * 16 + (lane & 15)) * (FP * 2) + kc;
                ldsm_x4(kh4, sKh + off);
                ldsm_x4(kl4, sKl + off);
                uint32_t b0h[2] = {kh4[0], kh4[2]}, b1h[2] = {kh4[1], kh4[3]};
                uint32_t b0l[2] = {kl4[0], kl4[2]}, b1l[2] = {kl4[1], kl4[3]};
                mma_bf16(s[2 * p],     qh[ks], b0h);
                mma_bf16(s[2 * p],     qh[ks], b0l);
                mma_bf16(s[2 * p],     ql[ks], b0h);
                mma_bf16(s[2 * p + 1], qh[ks], b1h);
                mma_bf16(s[2 * p + 1], qh[ks], b1l);
                mma_bf16(s[2 * p + 1], ql[ks], b1h);
            }
        }

        #pragma unroll
        for (int rh = 0; rh < 2; rh++) {
            float mx = -1e30f;
            #pragma unroll
            for (int nt = 0; nt < 8; nt++)
                mx = fmaxf(mx, fmaxf(s[nt][2 * rh], s[nt][2 * rh + 1]));
            mx = fmaxf(mx, __shfl_xor_sync(0xffffffffu, mx, 1));
            mx = fmaxf(mx, __shfl_xor_sync(0xffffffffu, mx, 2));
            float mnew = fmaxf(mrow[rh], mx);
            float corr = __expf(mrow[rh] - mnew);
            mrow[rh] = mnew;
            float rs = 0.f;
            #pragma unroll
            for (int nt = 0; nt < 8; nt++) {
                float p0 = __expf(s[nt][2 * rh] - mnew);
                float p1 = __expf(s[nt][2 * rh + 1] - mnew);
                s[nt][2 * rh] = p0;
                s[nt][2 * rh + 1] = p1;
                rs += p0 + p1;
            }
            rs += __shfl_xor_sync(0xffffffffu, rs, 1);
            rs += __shfl_xor_sync(0xffffffffu, rs, 2);
            lrow[rh] = lrow[rh] * corr + rs;
            #pragma unroll
            for (int nt = 0; nt < 8; nt++) {
                o[nt][2 * rh]     *= corr;
                o[nt][2 * rh + 1] *= corr;
            }
        }

        uint32_t ph[4][4], pl[4][4];
        #pragma unroll
        for (int ks = 0; ks < 4; ks++) {
            #pragma unroll
            for (int half = 0; half < 2; half++) {
                const float* sv = s[2 * ks + half];
                #pragma unroll
                for (int rr = 0; rr < 2; rr++) {
                    float v0 = sv[2 * rr], v1 = sv[2 * rr + 1];
                    bf16 h0, l0, h1, l1;
                    split_bf16(v0, h0, l0);
                    split_bf16(v1, h1, l1);
                    ph[ks][half * 2 + rr] = pack_bf16x2(__bfloat162float(h0),
                                                        __bfloat162float(h1));
                    pl[ks][half * 2 + rr] = pack_bf16x2(__bfloat162float(l0),
                                                        __bfloat162float(l1));
                }
            }
        }

        #pragma unroll
        for (int ks = 0; ks < 4; ks++) {
            #pragma unroll
            for (int p = 0; p < 4; p++) {
                uint32_t vh4[4], vl4[4];
                uint32_t off = (uint32_t)(ks * 16 + (lane & 15)) * (FP * 2)
                             + p * 32 + (lane >> 4) * 16;
                ldsm_x4_t(vh4, sVh + off);
                ldsm_x4_t(vl4, sVl + off);
                uint32_t b0h[2] = {vh4[0], vh4[1]}, b1h[2] = {vh4[2], vh4[3]};
                uint32_t b0l[2] = {vl4[0], vl4[1]}, b1l[2] = {vl4[2], vl4[3]};
                mma_bf16(o[2 * p],     ph[ks], b0h);
                mma_bf16(o[2 * p],     ph[ks], b0l);
                mma_bf16(o[2 * p],     pl[ks], b0h);
                mma_bf16(o[2 * p + 1], ph[ks], b1h);
                mma_bf16(o[2 * p + 1], ph[ks], b1l);
                mma_bf16(o[2 * p + 1], pl[ks], b1h);
            }
        }
    }

    const int erow = lane >> 2;
    const int ecol = (lane & 3) * 2;
    #pragma unroll
    for (int rh = 0; rh < 2; rh++) {
        float inv = 1.f / lrow[rh];
        int row = q0 + wid * 16 + erow + rh * 8;
        size_t rbase = (size_t)(b * 2048 + row) * 1024 + h * 64;
        #pragma unroll
        for (int nt = 0; nt < 8; nt++) {
            float v0 = o[nt][2 * rh] * inv;
            float v1 = o[nt][2 * rh + 1] * inv;
            bf16 h0, l0, h1, l1;
            split_bf16(v0, h0, l0);
            split_bf16(v1, h1, l1);
            size_t idx = rbase + nt * 8 + ecol;
            *(__nv_bfloat162*)(g_ctxh + idx) = __nv_bfloat162(h0, h1);
            *(__nv_bfloat162*)(g_ctxl + idx) = __nv_bfloat162(l0, l1);
        }
    }
}

// ---------------------------------------------------------------------------
extern "C" void kernel_launch(void* const* d_in, const int* in_sizes, int n_in,
                              void* d_out, int out_size)
{
    const float* x      = (const float*)d_in[0];
    const float* w_qkv  = (const float*)d_in[1];
    const float* w_proj = (const float*)d_in[2];
    float* out          = (float*)d_out;

    bf16 *xh, *xl, *wqh, *wql, *wph, *wpl, *ctxh, *ctxl;
    cudaGetSymbolAddress((void**)&xh, g_xh);
    cudaGetSymbolAddress((void**)&xl, g_xl);
    cudaGetSymbolAddress((void**)&wqh, g_wqh);
    cudaGetSymbolAddress((void**)&wql, g_wql);
    cudaGetSymbolAddress((void**)&wph, g_wph);
    cudaGetSymbolAddress((void**)&wpl, g_wpl);
    cudaGetSymbolAddress((void**)&ctxh, g_ctxh);
    cudaGetSymbolAddress((void**)&ctxl, g_ctxl);

    conv_split<<<(8192 * 1024 / 4 + 255) / 256, 256>>>(x, xh, xl, 8192 * 1024 / 4);
    conv_split<<<(3072 * 1024 / 4 + 255) / 256, 256>>>(w_qkv, wqh, wql, 3072 * 1024 / 4);
    conv_split<<<(1024 * 1024 / 4 + 255) / 256, 256>>>(w_proj, wph, wpl, 1024 * 1024 / 4);

    cudaFuncSetAttribute(hmma_gemm,
                         cudaFuncAttributeMaxDynamicSharedMemorySize, GEMM_SMEM);
    cudaFuncSetAttribute(flash_hmma,
                         cudaFuncAttributeMaxDynamicSharedMemorySize, FLASH_SMEM);

    // QKV: M=8192, N=3072 -> grid (24, 64)
    hmma_gemm<<<dim3(24, 64), 256, GEMM_SMEM>>>(xh, xl, wqh, wql, nullptr, 0, 0);

    // flash: 16 q-tiles x 64 (b,h)
    flash_hmma<<<dim3(16, 64), 256, FLASH_SMEM>>>();

    // proj: M=8192, N=1024 -> grid (8, 64)
    hmma_gemm<<<dim3(8, 64), 256, GEMM_SMEM>>>(ctxh, ctxl, wph, wpl, out, 1024, 1);
}

// round 16
// speedup vs baseline: 1.0370x; 1.0370x over previous
#include <cuda_runtime.h>
#include <cuda_bf16.h>
#include <math.h>
#include <stdint.h>

#define BB 4
#define LL 2048
#define DD 1024
#define HH 16
#define DHH 64

typedef __nv_bfloat16 bf16;

// ---------------- scratch (allocation-free device globals) ----------------
__device__ bf16 g_xh[(size_t)8192 * 1024], g_xl[(size_t)8192 * 1024];
__device__ bf16 g_wqh[(size_t)3072 * 1024], g_wql[(size_t)3072 * 1024];
__device__ bf16 g_wph[(size_t)1024 * 1024], g_wpl[(size_t)1024 * 1024];
__device__ bf16 g_qh[(size_t)64 * 2048 * 64], g_ql[(size_t)64 * 2048 * 64];
__device__ bf16 g_kh[(size_t)64 * 2048 * 64], g_kl[(size_t)64 * 2048 * 64];
__device__ bf16 g_vh[(size_t)64 * 2048 * 64], g_vl[(size_t)64 * 2048 * 64];
__device__ bf16 g_ctxh[(size_t)8192 * 1024], g_ctxl[(size_t)8192 * 1024];

// ---------------- PTX helpers ----------------
__device__ __forceinline__ uint32_t smem_u32(const void* p) {
    uint32_t a;
    asm("{ .reg .u64 t; cvta.to.shared.u64 t, %1; cvt.u32.u64 %0, t; }"
        : "=r"(a) : "l"(p));
    return a;
}
__device__ __forceinline__ void ldsm_x4(uint32_t* r, uint32_t addr) {
    asm volatile("ldmatrix.sync.aligned.m8n8.x4.shared.b16 {%0,%1,%2,%3}, [%4];"
                 : "=r"(r[0]), "=r"(r[1]), "=r"(r[2]), "=r"(r[3]) : "r"(addr));
}
__device__ __forceinline__ void ldsm_x4_t(uint32_t* r, uint32_t addr) {
    asm volatile("ldmatrix.sync.aligned.m8n8.x4.trans.shared.b16 {%0,%1,%2,%3}, [%4];"
                 : "=r"(r[0]), "=r"(r[1]), "=r"(r[2]), "=r"(r[3]) : "r"(addr));
}
__device__ __forceinline__ void mma_bf16(float* d, const uint32_t* a,
                                         const uint32_t* b) {
    asm volatile(
        "mma.sync.aligned.m16n8k16.row.col.f32.bf16.bf16.f32 "
        "{%0,%1,%2,%3}, {%4,%5,%6,%7}, {%8,%9}, {%0,%1,%2,%3};"
        : "+f"(d[0]), "+f"(d[1]), "+f"(d[2]), "+f"(d[3])
        : "r"(a[0]), "r"(a[1]), "r"(a[2]), "r"(a[3]), "r"(b[0]), "r"(b[1]));
}
#define CP_ASYNC16(dst, src) \
    asm volatile("cp.async.cg.shared.global [%0], [%1], 16;" \
                 :: "r"(dst), "l"(src) : "memory")
#define CP_COMMIT() asm volatile("cp.async.commit_group;" ::: "memory")
#define CP_WAIT0()  asm volatile("cp.async.wait_group 0;" ::: "memory")

__device__ __forceinline__ uint32_t pack_bf16x2(float a, float b) {
    __nv_bfloat162 t = __floats2bfloat162_rn(a, b);
    return *(uint32_t*)&t;
}
__device__ __forceinline__ void split_bf16(float v, bf16& h, bf16& l) {
    h = __float2bfloat16(v);
    l = __float2bfloat16(v - __bfloat162float(h));
}

// ---------------------------------------------------------------------------
// conv_split: fp32 -> (hi, lo) bf16, elementwise
// ---------------------------------------------------------------------------
__global__ void conv_split(const float* __restrict__ src, bf16* __restrict__ h,
                           bf16* __restrict__ l, int n4)
{
    int i = blockIdx.x * blockDim.x + threadIdx.x;
    if (i >= n4) return;
    float4 v = ((const float4*)src)[i];
    bf16 h0, l0, h1, l1, h2, l2, h3, l3;
    split_bf16(v.x, h0, l0); split_bf16(v.y, h1, l1);
    split_bf16(v.z, h2, l2); split_bf16(v.w, h3, l3);
    ((__nv_bfloat162*)h)[2 * i]     = __nv_bfloat162(h0, h1);
    ((__nv_bfloat162*)h)[2 * i + 1] = __nv_bfloat162(h2, h3);
    ((__nv_bfloat162*)l)[2 * i]     = __nv_bfloat162(l0, l1);
    ((__nv_bfloat162*)l)[2 * i + 1] = __nv_bfloat162(l2, l3);
}

// ---------------------------------------------------------------------------
// HMMA GEMM, tile 128x64x32 (R7 base): 8 warps 4x2, warp 32x32, 2 CTAs/SM.
// MMA emission in 3 PASSES over all 8 accumulators (hh* -> hl* -> lh*):
// RAW distance per accumulator goes 1 -> 8 to hide HMMA latency.
// mode 0: scatter bf16 hi/lo into g_q/g_k/g_v (q scaled). mode 1: fp32 -> Cp.
// ---------------------------------------------------------------------------
#define GP 40  // smem pitch in bf16 elems (80 B)

__global__ __launch_bounds__(256, 2) void hmma_gemm(
    const bf16* __restrict__ Ah_g, const bf16* __restrict__ Al_g,
    const bf16* __restrict__ Bh_g, const bf16* __restrict__ Bl_g,
    float* __restrict__ Cp, int ldc, int mode)
{
    __shared__ bf16 Ah[128][GP], Al[128][GP], Bh[64][GP], Bl[64][GP];

    const int tid  = threadIdx.x;
    const int wid  = tid >> 5;
    const int lane = tid & 31;
    const int m0   = blockIdx.y * 128;
    const int n0   = blockIdx.x * 64;
    const int wm   = (wid >> 1) * 32;   // 4 warps in m
    const int wn   = (wid & 1) * 32;    // 2 warps in n

    const uint32_t sAh = smem_u32(Ah), sAl = smem_u32(Al);
    const uint32_t sBh = smem_u32(Bh), sBl = smem_u32(Bl);

    const int arow = tid >> 2, apart = tid & 3;

    float c[2][4][4] = {};
    uint4 pA[2][2], pB[2];   // [hi/lo][it] / [hi/lo]

    {
        const bf16* Asrc[2] = {Ah_g, Al_g};
        const bf16* Bsrc[2] = {Bh_g, Bl_g};
        #pragma unroll
        for (int s = 0; s < 2; s++) {
            #pragma unroll
            for (int it = 0; it < 2; it++) {
                int row = arow + it * 64;
                pA[s][it] = *(const uint4*)(Asrc[s] + (size_t)(m0 + row) * 1024 + apart * 8);
            }
            pB[s] = *(const uint4*)(Bsrc[s] + (size_t)(n0 + arow) * 1024 + apart * 8);
        }
    }

    for (int ch = 0; ch < 32; ch++) {
        #pragma unroll
        for (int it = 0; it < 2; it++) {
            int row = arow + it * 64;
            *(uint4*)(&Ah[row][apart * 8]) = pA[0][it];
            *(uint4*)(&Al[row][apart * 8]) = pA[1][it];
        }
        *(uint4*)(&Bh[arow][apart * 8]) = pB[0];
        *(uint4*)(&Bl[arow][apart * 8]) = pB[1];
        __syncthreads();

        if (ch + 1 < 32) {
            const int k0 = (ch + 1) * 32;
            const bf16* Asrc[2] = {Ah_g, Al_g};
            const bf16* Bsrc[2] = {Bh_g, Bl_g};
            #pragma unroll
            for (int s = 0; s < 2; s++) {
                #pragma unroll
                for (int it = 0; it < 2; it++) {
                    int row = arow + it * 64;
                    pA[s][it] = *(const uint4*)(Asrc[s] + (size_t)(m0 + row) * 1024
                                                + k0 + apart * 8);
                }
                pB[s] = *(const uint4*)(Bsrc[s] + (size_t)(n0 + arow) * 1024
                                        + k0 + apart * 8);
            }
        }

        #pragma unroll
        for (int ks = 0; ks < 2; ks++) {
            const uint32_t kc = (uint32_t)(ks * 32 + (lane >> 4) * 16);
            uint32_t ah[2][4], al[2][4];
            #pragma unroll
            for (int mt = 0; mt < 2; mt++) {
                uint32_t off = (uint32_t)(wm + mt * 16 + (lane & 15)) * (GP * 2) + kc;
                ldsm_x4(ah[mt], sAh + off);
                ldsm_x4(al[mt], sAl + off);
            }
            uint32_t bh[4][2], bl[4][2];
            #pragma unroll
            for (int half = 0; half < 2; half++) {
                uint32_t r4h[4], r4l[4];
                uint32_t off = (uint32_t)(wn + half * 16 + (lane & 15)) * (GP * 2) + kc;
                ldsm_x4(r4h, sBh + off);
                ldsm_x4(r4l, sBl + off);
                bh[half * 2 + 0][0] = r4h[0]; bh[half * 2 + 0][1] = r4h[2];
                bh[half * 2 + 1][0] = r4h[1]; bh[half * 2 + 1][1] = r4h[3];
                bl[half * 2 + 0][0] = r4l[0]; bl[half * 2 + 0][1] = r4l[2];
                bl[half * 2 + 1][0] = r4l[1]; bl[half * 2 + 1][1] = r4l[3];
            }
            // PASS 1: hh into all 8 accumulators
            #pragma unroll
            for (int mt = 0; mt < 2; mt++)
                #pragma unroll
                for (int nt = 0; nt < 4; nt++)
                    mma_bf16(c[mt][nt], ah[mt], bh[nt]);
            // PASS 2: hl
            #pragma unroll
            for (int mt = 0; mt < 2; mt++)
                #pragma unroll
                for (int nt = 0; nt < 4; nt++)
                    mma_bf16(c[mt][nt], ah[mt], bl[nt]);
            // PASS 3: lh
            #pragma unroll
            for (int mt = 0; mt < 2; mt++)
                #pragma unroll
                for (int nt = 0; nt < 4; nt++)
                    mma_bf16(c[mt][nt], al[mt], bh[nt]);
        }
        __syncthreads();
    }

    const int erow = lane >> 2;
    const int ecol = (lane & 3) * 2;

    if (mode == 1) {
        #pragma unroll
        for (int mt = 0; mt < 2; mt++)
            #pragma unroll
            for (int nt = 0; nt < 4; nt++) {
                int row = m0 + wm + mt * 16 + erow;
                int col = n0 + wn + nt * 8 + ecol;
                *(float2*)&Cp[(size_t)row * ldc + col] =
                    make_float2(c[mt][nt][0], c[mt][nt][1]);
                *(float2*)&Cp[(size_t)(row + 8) * ldc + col] =
                    make_float2(c[mt][nt][2], c[mt][nt][3]);
            }
    } else {
        const int which = n0 >> 10;
        bf16* dsth = (which == 0) ? g_qh : (which == 1) ? g_kh : g_vh;
        bf16* dstl = (which == 0) ? g_ql : (which == 1) ? g_kl : g_vl;
        const float sc = (which == 0) ? 0.125f : 1.0f;
        #pragma unroll
        for (int mt = 0; mt < 2; mt++)
            #pragma unroll
            for (int nt = 0; nt < 4; nt++) {
                int col = (n0 & 1023) + wn + nt * 8 + ecol;
                int h = col >> 6, dh = col & 63;
                #pragma unroll
                for (int rr = 0; rr < 2; rr++) {
                    int row = m0 + wm + mt * 16 + erow + rr * 8;
                    int b = row >> 11, l = row & 2047;
                    size_t base = ((size_t)((b << 4) + h) * 2048 + l) * 64 + dh;
                    float v0 = c[mt][nt][rr * 2 + 0] * sc;
                    float v1 = c[mt][nt][rr * 2 + 1] * sc;
                    bf16 h0, l0, h1, l1;
                    split_bf16(v0, h0, l0);
                    split_bf16(v1, h1, l1);
                    *(__nv_bfloat162*)(dsth + base) = __nv_bfloat162(h0, h1);
                    *(__nv_bfloat162*)(dstl + base) = __nv_bfloat162(l0, l1);
                }
            }
    }
}

// ---------------------------------------------------------------------------
// Flash attention, HMMA. MMA groups reordered to interleave the two
// accumulators of each pair (RAW distance 1 -> 2) and pass-ordered.
// ---------------------------------------------------------------------------
#define FP 72
#define FQ (128 * FP * 2)
#define FMAT (64 * FP * 2)
#define FSTAGE (4 * FMAT)
#define FLASH_SMEM (2 * FQ + 2 * FSTAGE)

__global__ __launch_bounds__(256) void flash_hmma()
{
    extern __shared__ char smem[];
    const uint32_t sb = smem_u32(smem);
    const uint32_t sQh = sb, sQl = sb + FQ;
    const uint32_t sKV = sb + 2 * FQ;

    const int tid  = threadIdx.x;
    const int wid  = tid >> 5;
    const int lane = tid & 31;
    const int bh   = blockIdx.y;
    const int q0   = blockIdx.x * 128;
    const int b    = bh >> 4;
    const int h    = bh & 15;

    const bf16* kvg[4] = {g_kh + (size_t)bh * 2048 * 64, g_kl + (size_t)bh * 2048 * 64,
                          g_vh + (size_t)bh * 2048 * 64, g_vl + (size_t)bh * 2048 * 64};

    {
        const bf16* qh_g = g_qh + (size_t)bh * 2048 * 64;
        const bf16* ql_g = g_ql + (size_t)bh * 2048 * 64;
        #pragma unroll
        for (int it = 0; it < 4; it++) {
            int i = tid + it * 256;
            int r = i >> 3, part = i & 7;
            uint4 v = *(const uint4*)(qh_g + (size_t)(q0 + r) * 64 + part * 8);
            *(uint4*)(smem + r * (FP * 2) + part * 16) = v;
            uint4 w = *(const uint4*)(ql_g + (size_t)(q0 + r) * 64 + part * 8);
            *(uint4*)(smem + FQ + r * (FP * 2) + part * 16) = w;
        }
    }

    #pragma unroll
    for (int it = 0; it < 8; it++) {
        int i = tid + it * 256;
        int mat = i >> 9, r = (i >> 3) & 63, part = i & 7;
        const bf16* src = kvg[mat] + (size_t)r * 64 + part * 8;
        uint32_t dst = sKV + mat * FMAT + r * (FP * 2) + part * 16;
        CP_ASYNC16(dst, src);
    }
    CP_COMMIT();
    __syncthreads();

    uint32_t qh[4][4], ql[4][4];
    #pragma unroll
    for (int ks = 0; ks < 4; ks++) {
        uint32_t off = (uint32_t)(wid * 16 + (lane & 15)) * (FP * 2)
                     + ks * 32 + (lane >> 4) * 16;
        ldsm_x4(qh[ks], sQh + off);
        ldsm_x4(ql[ks], sQl + off);
    }

    float o[8][4] = {};
    float mrow[2] = {-1e30f, -1e30f};
    float lrow[2] = {0.f, 0.f};

    for (int kb = 0; kb < 32; kb++) {
        CP_WAIT0();
        __syncthreads();

        if (kb + 1 < 32) {
            const uint32_t stg = sKV + ((kb + 1) & 1) * FSTAGE;
            const int krow0 = (kb + 1) * 64;
            #pragma unroll
            for (int it = 0; it < 8; it++) {
                int i = tid + it * 256;
                int mat = i >> 9, r = (i >> 3) & 63, part = i & 7;
                const bf16* src = kvg[mat] + (size_t)(krow0 + r) * 64 + part * 8;
                uint32_t dst = stg + mat * FMAT + r * (FP * 2) + part * 16;
                CP_ASYNC16(dst, src);
            }
            CP_COMMIT();
        }

        const uint32_t stg = sKV + (kb & 1) * FSTAGE;
        const uint32_t sKh = stg, sKl = stg + FMAT;
        const uint32_t sVh = stg + 2 * FMAT, sVl = stg + 3 * FMAT;

        float s[8][4] = {};
        #pragma unroll
        for (int ks = 0; ks < 4; ks++) {
            const uint32_t kc = (uint32_t)(ks * 32 + (lane >> 4) * 16);
            #pragma unroll
            for (int p = 0; p < 4; p++) {
                uint32_t kh4[4], kl4[4];
                uint32_t off = (uint32_t)(p * 16 + (lane & 15)) * (FP * 2) + kc;
                ldsm_x4(kh4, sKh + off);
                ldsm_x4(kl4, sKl + off);
                uint32_t b0h[2] = {kh4[0], kh4[2]}, b1h[2] = {kh4[1], kh4[3]};
                uint32_t b0l[2] = {kl4[0], kl4[2]}, b1l[2] = {kl4[1], kl4[3]};
                // interleaved: acc pair alternates, passes hh -> hl -> lh
                mma_bf16(s[2 * p],     qh[ks], b0h);
                mma_bf16(s[2 * p + 1], qh[ks], b1h);
                mma_bf16(s[2 * p],     qh[ks], b0l);
                mma_bf16(s[2 * p + 1], qh[ks], b1l);
                mma_bf16(s[2 * p],     ql[ks], b0h);
                mma_bf16(s[2 * p + 1], ql[ks], b1h);
            }
        }

        #pragma unroll
        for (int rh = 0; rh < 2; rh++) {
            float mx = -1e30f;
            #pragma unroll
            for (int nt = 0; nt < 8; nt++)
                mx = fmaxf(mx, fmaxf(s[nt][2 * rh], s[nt][2 * rh + 1]));
            mx = fmaxf(mx, __shfl_xor_sync(0xffffffffu, mx, 1));
            mx = fmaxf(mx, __shfl_xor_sync(0xffffffffu, mx, 2));
            float mnew = fmaxf(mrow[rh], mx);
            float corr = __expf(mrow[rh] - mnew);
            mrow[rh] = mnew;
            float rs = 0.f;
            #pragma unroll
            for (int nt = 0; nt < 8; nt++) {
                float p0 = __expf(s[nt][2 * rh] - mnew);
                float p1 = __expf(s[nt][2 * rh + 1] - mnew);
                s[nt][2 * rh] = p0;
                s[nt][2 * rh + 1] = p1;
                rs += p0 + p1;
            }
            rs += __shfl_xor_sync(0xffffffffu, rs, 1);
            rs += __shfl_xor_sync(0xffffffffu, rs, 2);
            lrow[rh] = lrow[rh] * corr + rs;
            #pragma unroll
            for (int nt = 0; nt < 8; nt++) {
                o[nt][2 * rh]     *= corr;
                o[nt][2 * rh + 1] *= corr;
            }
        }

        uint32_t ph[4][4], pl[4][4];
        #pragma unroll
        for (int ks = 0; ks < 4; ks++) {
            #pragma unroll
            for (int half = 0; half < 2; half++) {
                const float* sv = s[2 * ks + half];
                #pragma unroll
                for (int rr = 0; rr < 2; rr++) {
                    float v0 = sv[2 * rr], v1 = sv[2 * rr + 1];
                    bf16 h0, l0, h1, l1;
                    split_bf16(v0, h0, l0);
                    split_bf16(v1, h1, l1);
                    ph[ks][half * 2 + rr] = pack_bf16x2(__bfloat162float(h0),
                                                        __bfloat162float(h1));
                    pl[ks][half * 2 + rr] = pack_bf16x2(__bfloat162float(l0),
                                                        __bfloat162float(l1));
                }
            }
        }

        #pragma unroll
        for (int ks = 0; ks < 4; ks++) {
            #pragma unroll
            for (int p = 0; p < 4; p++) {
                uint32_t vh4[4], vl4[4];
                uint32_t off = (uint32_t)(ks * 16 + (lane & 15)) * (FP * 2)
                             + p * 32 + (lane >> 4) * 16;
                ldsm_x4_t(vh4, sVh + off);
                ldsm_x4_t(vl4, sVl + off);
                uint32_t b0h[2] = {vh4[0], vh4[1]}, b1h[2] = {vh4[2], vh4[3]};
                uint32_t b0l[2] = {vl4[0], vl4[1]}, b1l[2] = {vl4[2], vl4[3]};
                // interleaved accumulator pair, passes hh -> hl -> lh
                mma_bf16(o[2 * p],     ph[ks], b0h);
                mma_bf16(o[2 * p + 1], ph[ks], b1h);
                mma_bf16(o[2 * p],     ph[ks], b0l);
                mma_bf16(o[2 * p + 1], ph[ks], b1l);
                mma_bf16(o[2 * p],     pl[ks], b0h);
                mma_bf16(o[2 * p + 1], pl[ks], b1h);
            }
        }
    }

    const int erow = lane >> 2;
    const int ecol = (lane & 3) * 2;
    #pragma unroll
    for (int rh = 0; rh < 2; rh++) {
        float inv = 1.f / lrow[rh];
        int row = q0 + wid * 16 + erow + rh * 8;
        size_t rbase = (size_t)(b * 2048 + row) * 1024 + h * 64;
        #pragma unroll
        for (int nt = 0; nt < 8; nt++) {
            float v0 = o[nt][2 * rh] * inv;
            float v1 = o[nt][2 * rh + 1] * inv;
            bf16 h0, l0, h1, l1;
            split_bf16(v0, h0, l0);
            split_bf16(v1, h1, l1);
            size_t idx = rbase + nt * 8 + ecol;
            *(__nv_bfloat162*)(g_ctxh + idx) = __nv_bfloat162(h0, h1);
            *(__nv_bfloat162*)(g_ctxl + idx) = __nv_bfloat162(l0, l1);
        }
    }
}

// ---------------------------------------------------------------------------
extern "C" void kernel_launch(void* const* d_in, const int* in_sizes, int n_in,
                              void* d_out, int out_size)
{
    const float* x      = (const float*)d_in[0];
    const float* w_qkv  = (const float*)d_in[1];
    const float* w_proj = (const float*)d_in[2];
    float* out          = (float*)d_out;

    bf16 *xh, *xl, *wqh, *wql, *wph, *wpl, *ctxh, *ctxl;
    cudaGetSymbolAddress((void**)&xh, g_xh);
    cudaGetSymbolAddress((void**)&xl, g_xl);
    cudaGetSymbolAddress((void**)&wqh, g_wqh);
    cudaGetSymbolAddress((void**)&wql, g_wql);
    cudaGetSymbolAddress((void**)&wph, g_wph);
    cudaGetSymbolAddress((void**)&wpl, g_wpl);
    cudaGetSymbolAddress((void**)&ctxh, g_ctxh);
    cudaGetSymbolAddress((void**)&ctxl, g_ctxl);

    conv_split<<<(8192 * 1024 / 4 + 255) / 256, 256>>>(x, xh, xl, 8192 * 1024 / 4);
    conv_split<<<(3072 * 1024 / 4 + 255) / 256, 256>>>(w_qkv, wqh, wql, 3072 * 1024 / 4);
    conv_split<<<(1024 * 1024 / 4 + 255) / 256, 256>>>(w_proj, wph, wpl, 1024 * 1024 / 4);

    cudaFuncSetAttribute(flash_hmma,
                         cudaFuncAttributeMaxDynamicSharedMemorySize, FLASH_SMEM);

    // QKV: M=8192, N=3072 -> grid (48, 64)
    hmma_gemm<<<dim3(48, 64), 256>>>(xh, xl, wqh, wql, nullptr, 0, 0);

    // flash: 16 q-tiles x 64 (b,h)
    flash_hmma<<<dim3(16, 64), 256, FLASH_SMEM>>>();

    // proj: M=8192, N=1024 -> grid (16, 64)
    hmma_gemm<<<dim3(16, 64), 256>>>(ctxh, ctxl, wph, wpl, out, 1024, 1);
}